// round 12
// baseline (speedup 1.0000x reference)
#include <cuda_runtime.h>
#include <cuda_bf16.h>
#include <cstdint>
#include <cstddef>

#define NSN  100000
#define NMD  50000
#define EE   600000
#define D    128
#define HOR  8
#define NEG  0.2f
#define GLOG 128   // blocks for k_rollall (<= SM count: all co-resident)

// ---------------- device scratch ----------------
__device__ float    d_xl[(size_t)NSN * D];
__device__ float    d_xr[(size_t)NMD * D];
__device__ float    d_ew[EE];
__device__ float    d_ssum[NMD];
__device__ float    d_csrc[NSN];
__device__ __align__(16) float d_gacc[D];
__device__ __align__(16) float d_inp[D];
__device__ __align__(16) float d_h[D];
__device__ __align__(16) float d_c[D];
__device__ __align__(16) float d_h2g[D];
__device__ float    d_pm_best[2][GLOG];
__device__ int      d_pm_bi[2][GLOG];
__device__ float    d_pm_bl[2][GLOG];
__device__ float    d_pm_lm[2][GLOG];
__device__ float    d_pm_ls[2][GLOG];
__device__ uint2    d_keys[HOR];
__device__ int      d_is64;
__device__ int      d_ready[HOR];
__device__ int      d_arr[HOR];
#define WSTRIDE 136
__device__ __align__(16) uint32_t d_wphl[64 * WSTRIDE];
__device__ __align__(16) uint32_t d_wpll[64 * WSTRIDE];
__device__ __align__(16) uint32_t d_wphr[64 * WSTRIDE];
__device__ __align__(16) uint32_t d_wplr[64 * WSTRIDE];
// transposed LSTM weights: [k][rowpair] float2
__device__ __align__(16) float2 d_wihT[D * 256];
__device__ __align__(16) float2 d_whhT[D * 256];

// ---------------- helpers ----------------
__device__ __forceinline__ int eidx(const void* ei, int is64, long long pos) {
    return is64 ? (int)((const long long*)ei)[pos] : ((const int*)ei)[pos];
}
__device__ __forceinline__ float neginf() { return __int_as_float((int)0xff800000); }

__device__ __forceinline__ uint2 tf2x32(unsigned k0, unsigned k1, unsigned x0, unsigned x1) {
    unsigned k2 = k0 ^ k1 ^ 0x1BD11BDAu;
    x0 += k0; x1 += k1;
#define TFR(r) { x0 += x1; x1 = (x1 << (r)) | (x1 >> (32 - (r))); x1 ^= x0; }
    TFR(13) TFR(15) TFR(26) TFR(6)   x0 += k1; x1 += k2 + 1u;
    TFR(17) TFR(29) TFR(16) TFR(24)  x0 += k2; x1 += k0 + 2u;
    TFR(13) TFR(15) TFR(26) TFR(6)   x0 += k0; x1 += k1 + 3u;
    TFR(17) TFR(29) TFR(16) TFR(24)  x0 += k1; x1 += k2 + 4u;
    TFR(13) TFR(15) TFR(26) TFR(6)   x0 += k2; x1 += k0 + 5u;
#undef TFR
    return make_uint2(x0, x1);
}

__device__ __forceinline__ void lsmerge(float& M, float& S, float m, float s) {
    if (s > 0.f) {
        if (m > M) { S = S * expf(M - m) + s; M = m; }
        else       { S += s * expf(m - M); }
    }
}

__device__ __forceinline__ void mma_bf16(float* c, const uint32_t* a, uint32_t b0, uint32_t b1) {
    asm volatile(
        "mma.sync.aligned.m16n8k16.row.col.f32.bf16.bf16.f32 "
        "{%0,%1,%2,%3}, {%4,%5,%6,%7}, {%8,%9}, {%0,%1,%2,%3};"
        : "+f"(c[0]), "+f"(c[1]), "+f"(c[2]), "+f"(c[3])
        : "r"(a[0]), "r"(a[1]), "r"(a[2]), "r"(a[3]), "r"(b0), "r"(b1));
}

__device__ __forceinline__ uint32_t pack_hi(float e, float o) {
    unsigned a = __bfloat16_as_ushort(__float2bfloat16_rn(e));
    unsigned b = __bfloat16_as_ushort(__float2bfloat16_rn(o));
    return a | (b << 16);
}
__device__ __forceinline__ uint32_t pack_lo(float e, float o) {
    float he = __bfloat162float(__float2bfloat16_rn(e));
    float ho = __bfloat162float(__float2bfloat16_rn(o));
    unsigned a = __bfloat16_as_ushort(__float2bfloat16_rn(e - he));
    unsigned b = __bfloat16_as_ushort(__float2bfloat16_rn(o - ho));
    return a | (b << 16);
}

// ---------------- init ----------------
__global__ void k_init(const void* ei) {
    int i = blockIdx.x * blockDim.x + threadIdx.x;
    if (i < NMD) d_ssum[i] = 0.f;
    if (i < NSN) d_csrc[i] = 0.f;
    if (i < D) { d_gacc[i] = 0.f; d_h[i] = 0.f; d_c[i] = 0.f; }
    if (i < HOR) { d_ready[i] = 0; d_arr[i] = 0; }
    if (i == 0) {
        const int* p = (const int*)ei;
        int all0 = 1;
        for (int j = 1; j < 201; j += 2) all0 &= (p[j] == 0);
        d_is64 = all0;
        for (int j = 0; j < HOR; j++) {
            uint2 r = tf2x32(0u, 42u, 0u, (unsigned)j);
            d_keys[j] = make_uint2(r.x, r.y);
        }
    }
}

// ---------------- W [n][k] -> packed bf16 hi/lo [kp][n] (stride 136) ----------------
__global__ void k_wconv(const float* __restrict__ Wl, const float* __restrict__ Wr) {
    int idx = blockIdx.x * blockDim.x + threadIdx.x;
    if (idx >= 64 * 128) return;
    int kp = idx >> 7, n = idx & 127;
    int o = kp * WSTRIDE + n;
    float le = Wl[n * D + 2 * kp], lo = Wl[n * D + 2 * kp + 1];
    d_wphl[o] = pack_hi(le, lo);
    d_wpll[o] = pack_lo(le, lo);
    float re = Wr[n * D + 2 * kp], ro = Wr[n * D + 2 * kp + 1];
    d_wphr[o] = pack_hi(re, ro);
    d_wplr[o] = pack_lo(re, ro);
}

// ---------------- transpose LSTM weights ----------------
__global__ void k_lstmT(const float* __restrict__ Wih, const float* __restrict__ Whh) {
    int idx = blockIdx.x * blockDim.x + threadIdx.x;
    if (idx >= D * 256) return;
    int k = idx >> 8, rp = idx & 255;
    d_wihT[idx] = make_float2(Wih[(2 * rp) * D + k], Wih[(2 * rp + 1) * D + k]);
    d_whhT[idx] = make_float2(Whh[(2 * rp) * D + k], Whh[(2 * rp + 1) * D + k]);
}

// ---------------- HMMA GEMM ----------------
#define SM_GB (64 * WSTRIDE)
__global__ void __launch_bounds__(256, 2) k_gemm_mma(const float* __restrict__ X,
                                                     const uint32_t* __restrict__ gbh,
                                                     const uint32_t* __restrict__ gbl,
                                                     float* __restrict__ Y, int rows) {
    extern __shared__ uint32_t bs[];
    uint32_t* Bh = bs;
    uint32_t* Bl = bs + SM_GB;
    for (int i = threadIdx.x; i < SM_GB / 4; i += 256) {
        ((uint4*)Bh)[i] = ((const uint4*)gbh)[i];
        ((uint4*)Bl)[i] = ((const uint4*)gbl)[i];
    }
    __syncthreads();
    int w = threadIdx.x >> 5, lane = threadIdx.x & 31;
    int q = lane & 3, g = lane >> 2;
    int r0 = blockIdx.x * 128 + w * 16 + g;
    const float* x0 = X + (size_t)(r0 < rows ? r0 : rows - 1) * D;
    const float* x1 = X + (size_t)(r0 + 8 < rows ? r0 + 8 : rows - 1) * D;
    float acc[16][4];
#pragma unroll
    for (int nt = 0; nt < 16; nt++) { acc[nt][0] = acc[nt][1] = acc[nt][2] = acc[nt][3] = 0.f; }
#pragma unroll
    for (int k8 = 0; k8 < 8; k8++) {
        int c0 = k8 * 16 + 2 * q;
        float2 p0 = *(const float2*)(x0 + c0);
        float2 p1 = *(const float2*)(x1 + c0);
        float2 p2 = *(const float2*)(x0 + c0 + 8);
        float2 p3 = *(const float2*)(x1 + c0 + 8);
        uint32_t ah[4], al[4];
        ah[0] = pack_hi(p0.x, p0.y); al[0] = pack_lo(p0.x, p0.y);
        ah[1] = pack_hi(p1.x, p1.y); al[1] = pack_lo(p1.x, p1.y);
        ah[2] = pack_hi(p2.x, p2.y); al[2] = pack_lo(p2.x, p2.y);
        ah[3] = pack_hi(p3.x, p3.y); al[3] = pack_lo(p3.x, p3.y);
        int kb0 = (k8 * 8 + q) * WSTRIDE + g;
        int kb1 = (k8 * 8 + q + 4) * WSTRIDE + g;
#pragma unroll
        for (int nt = 0; nt < 16; nt++) {
            uint32_t bh0 = Bh[kb0 + nt * 8];
            uint32_t bh1 = Bh[kb1 + nt * 8];
            uint32_t bl0 = Bl[kb0 + nt * 8];
            uint32_t bl1 = Bl[kb1 + nt * 8];
            mma_bf16(acc[nt], ah, bh0, bh1);
            mma_bf16(acc[nt], ah, bl0, bl1);
            mma_bf16(acc[nt], al, bh0, bh1);
        }
    }
    bool w0 = r0 < rows, w1 = (r0 + 8) < rows;
#pragma unroll
    for (int nt = 0; nt < 16; nt++) {
        int col = nt * 8 + 2 * q;
        if (w0) *(float2*)(Y + (size_t)r0 * D + col) = make_float2(acc[nt][0], acc[nt][1]);
        if (w1) *(float2*)(Y + (size_t)(r0 + 8) * D + col) = make_float2(acc[nt][2], acc[nt][3]);
    }
}

// ---------------- fused edge pass ----------------
__global__ void __launch_bounds__(256) k_edge12(const void* __restrict__ ei,
                                                const float* __restrict__ att) {
    int lane = threadIdx.x & 31;
    int wid = (blockIdx.x * blockDim.x + threadIdx.x) >> 5;
    int nw = (gridDim.x * blockDim.x) >> 5;
    int is64 = d_is64;
    float4 av = ((const float4*)att)[lane];
    for (int e = wid * 2; e < EE; e += nw * 2) {
        int s1 = eidx(ei, is64, e);
        int dd1 = eidx(ei, is64, (long long)EE + e);
        int s2 = eidx(ei, is64, e + 1);
        int dd2 = eidx(ei, is64, (long long)EE + e + 1);
        float4 l1 = ((const float4*)(d_xl + (size_t)s1 * D))[lane];
        float4 r1 = ((const float4*)(d_xr + (size_t)dd1 * D))[lane];
        float4 l2 = ((const float4*)(d_xl + (size_t)s2 * D))[lane];
        float4 r2 = ((const float4*)(d_xr + (size_t)dd2 * D))[lane];
        float zx, zy, zz, zw, p1, p2;
        zx = l1.x + r1.x; zy = l1.y + r1.y; zz = l1.z + r1.z; zw = l1.w + r1.w;
        zx = zx > 0.f ? zx : NEG * zx; zy = zy > 0.f ? zy : NEG * zy;
        zz = zz > 0.f ? zz : NEG * zz; zw = zw > 0.f ? zw : NEG * zw;
        p1 = av.x * zx + av.y * zy + av.z * zz + av.w * zw;
        zx = l2.x + r2.x; zy = l2.y + r2.y; zz = l2.z + r2.z; zw = l2.w + r2.w;
        zx = zx > 0.f ? zx : NEG * zx; zy = zy > 0.f ? zy : NEG * zy;
        zz = zz > 0.f ? zz : NEG * zz; zw = zw > 0.f ? zw : NEG * zw;
        p2 = av.x * zx + av.y * zy + av.z * zz + av.w * zw;
#pragma unroll
        for (int o = 16; o; o >>= 1) {
            p1 += __shfl_xor_sync(~0u, p1, o);
            p2 += __shfl_xor_sync(~0u, p2, o);
        }
        if (lane == 0) {
            float e1 = expf(p1), e2 = expf(p2);
            d_ew[e] = e1;     atomicAdd(&d_ssum[dd1], e1);
            d_ew[e + 1] = e2; atomicAdd(&d_ssum[dd2], e2);
        }
    }
}

__global__ void k_edge3a(const void* __restrict__ ei) {
    int i = blockIdx.x * blockDim.x + threadIdx.x;
    if (i >= EE) return;
    int is64 = d_is64;
    int src = eidx(ei, is64, i);
    int dst = eidx(ei, is64, (long long)EE + i);
    atomicAdd(&d_csrc[src], d_ew[i] / d_ssum[dst]);
}

__global__ void __launch_bounds__(256) k_dense() {
    __shared__ float sg[D];
    int lane = threadIdx.x & 31, w = threadIdx.x >> 5;
    if (threadIdx.x < D) sg[threadIdx.x] = 0.f;
    __syncthreads();
    int gw = blockIdx.x * 8 + w;
    int nw = gridDim.x * 8;
    float4 acc = make_float4(0.f, 0.f, 0.f, 0.f);
    for (int r = gw; r < NSN; r += nw) {
        float cv = d_csrc[r];
        float4 v = ((const float4*)(d_xl + (size_t)r * D))[lane];
        acc.x += cv * v.x; acc.y += cv * v.y; acc.z += cv * v.z; acc.w += cv * v.w;
    }
    atomicAdd(&sg[lane * 4 + 0], acc.x);
    atomicAdd(&sg[lane * 4 + 1], acc.y);
    atomicAdd(&sg[lane * 4 + 2], acc.z);
    atomicAdd(&sg[lane * 4 + 3], acc.w);
    __syncthreads();
    if (threadIdx.x < D) atomicAdd(&d_gacc[threadIdx.x], sg[threadIdx.x]);
}

__global__ void k_fing(const float* __restrict__ conv_bias) {
    int t = threadIdx.x;
    if (t < D) d_inp[t] = d_gacc[t] * (1.0f / (float)NMD) + conv_bias[t];
}

// ---------------- fused 8-step rollout (single launch, flag pipeline) ----------------
__global__ void __launch_bounds__(256) k_rollall(
    const float* __restrict__ bih, const float* __restrict__ bhh,
    const float* __restrict__ W1,  const float* __restrict__ b1,
    const float* __restrict__ W2,  const float* __restrict__ b2,
    const float* __restrict__ emb, float* __restrict__ out) {
    __shared__ float si[D], sh[D], sg[4 * D], snh[D], sh2[D];
    __shared__ float wbest[8], wbl[8], wlm[8], wls[8];
    __shared__ int wbi[8], sAct;
    int t = threadIdx.x, lane = t & 31, w = t >> 5;
    const float NI = neginf();
    int q = lane & 3, g = lane >> 2;

    for (int step = 0; step < HOR; step++) {
        int wp = step & 1, pmr = (step - 1) & 1;
        if (blockIdx.x == 0) {
            if (step > 0) {
                // wait for all blocks' phase-B of previous step
                if (t == 0) { while (atomicAdd(&d_arr[step - 1], 0) < GLOG) __nanosleep(32); }
                __syncthreads();
                __threadfence();
                if (t < 32) {
                    float B = NI, BL = 0.f; int BI = 0x7fffffff; float M = NI, S = 0.f;
                    for (int i = lane; i < GLOG; i += 32) {
                        float b = d_pm_best[pmr][i]; int bidx = d_pm_bi[pmr][i];
                        if (b > B || (b == B && bidx < BI)) { B = b; BI = bidx; BL = d_pm_bl[pmr][i]; }
                        lsmerge(M, S, d_pm_lm[pmr][i], d_pm_ls[pmr][i]);
                    }
#pragma unroll
                    for (int o = 16; o; o >>= 1) {
                        float ob = __shfl_xor_sync(~0u, B, o);
                        int oi = __shfl_xor_sync(~0u, BI, o);
                        float ol = __shfl_xor_sync(~0u, BL, o);
                        if (ob > B || (ob == B && oi < BI)) { B = ob; BI = oi; BL = ol; }
                        float om = __shfl_xor_sync(~0u, M, o);
                        float os = __shfl_xor_sync(~0u, S, o);
                        lsmerge(M, S, om, os);
                    }
                    if (lane == 0) {
                        out[step - 1] = (float)BI;
                        out[HOR + step - 1] = BL - (M + logf(S));
                        sAct = BI;
                    }
                }
                __syncthreads();
                if (t < D) si[t] = emb[(size_t)sAct * D + t];
            } else {
                if (t < D) si[t] = d_inp[t];
            }
            if (t < D) sh[t] = d_h[t];
            __syncthreads();
            // LSTM gates (transposed weights: thread t -> rows 2t, 2t+1)
            {
                float2 bi_ = ((const float2*)bih)[t];
                float2 bh_ = ((const float2*)bhh)[t];
                float ax = bi_.x + bh_.x, ay = bi_.y + bh_.y;
#pragma unroll 4
                for (int k = 0; k < D; k++) {
                    float2 wi = d_wihT[k * 256 + t];
                    float2 wh = d_whhT[k * 256 + t];
                    float xk = si[k], hk = sh[k];
                    ax += wi.x * xk + wh.x * hk;
                    ay += wi.y * xk + wh.y * hk;
                }
                sg[2 * t] = ax; sg[2 * t + 1] = ay;
            }
            __syncthreads();
            if (t < D) {
                float ig = 1.f / (1.f + expf(-sg[t]));
                float fg = 1.f / (1.f + expf(-sg[D + t]));
                float gg = tanhf(sg[2 * D + t]);
                float og = 1.f / (1.f + expf(-sg[3 * D + t]));
                float c = fg * d_c[t] + ig * gg;
                float h = og * tanhf(c);
                snh[t] = h;
                d_c[t] = c; d_h[t] = h;
                if (step == HOR - 1) { out[2 * HOR + t] = h; out[2 * HOR + D + t] = c; }
            }
            __syncthreads();
            if (t < D) {
                float a0 = b1[t], a1 = 0.f;
                const float4* w1 = (const float4*)(W1 + (size_t)t * D);
#pragma unroll 8
                for (int k = 0; k < 32; k += 2) {
                    float4 a = w1[k];     float4 hv = *(const float4*)(snh + 4 * k);
                    float4 b = w1[k + 1]; float4 h2v = *(const float4*)(snh + 4 * k + 4);
                    a0 += a.x * hv.x + a.y * hv.y + a.z * hv.z + a.w * hv.w;
                    a1 += b.x * h2v.x + b.y * h2v.y + b.z * h2v.z + b.w * h2v.w;
                }
                float a2 = a0 + a1;
                a2 = a2 > 0.f ? a2 : 0.f;
                sh2[t] = a2;
                d_h2g[t] = a2;
            }
            __syncthreads();
            if (t == 0) { __threadfence(); atomicExch(&d_ready[step], 1); }
        } else {
            if (t == 0) { while (atomicAdd(&d_ready[step], 0) == 0) __nanosleep(32); }
            __syncthreads();
            if (t < D) sh2[t] = __ldcg(&d_h2g[t]);
            __syncthreads();
        }

        // ---- phase B: logits + gumbel + online softmax (quad-parallel) ----
        uint2 key = d_keys[step];
        float4 hreg[8];
#pragma unroll
        for (int i = 0; i < 8; i++) hreg[i] = ((const float4*)sh2)[i * 4 + q];
        int gw = (blockIdx.x * blockDim.x + t) >> 5;
        int nw = (GLOG * 256) >> 5;
        float best = NI, bl = 0.f; int bi = 0x7fffffff;
        float lm = NI, ls = 0.f;
        for (int base = gw * 32; base < NMD; base += nw * 32) {
            float myl = 0.f;
#pragma unroll
            for (int it = 0; it < 4; it++) {
                int row = base + it * 8 + g;
                float p = 0.f;
                if (row < NMD) {
                    const float4* wr = (const float4*)(W2 + (size_t)row * D);
#pragma unroll
                    for (int i = 0; i < 8; i++) {
                        float4 wv = wr[i * 4 + q];
                        float4 hv = hreg[i];
                        p += wv.x * hv.x + wv.y * hv.y + wv.z * hv.z + wv.w * hv.w;
                    }
                }
                p += __shfl_xor_sync(~0u, p, 1);
                p += __shfl_xor_sync(~0u, p, 2);
                if (q == it) myl = p;
            }
            int myrow = base + q * 8 + g;
            if (myrow < NMD) {
                myl += b2[myrow];
                uint2 tr = tf2x32(key.x, key.y, 0u, (unsigned)myrow);
                unsigned bits = tr.x ^ tr.y;
                float u = __uint_as_float((bits >> 9) | 0x3f800000u) - 1.0f;
                if (u == 0.f) u = 1.17549435e-38f;
                float score = myl - logf(-logf(u));
                if (score > best || (score == best && myrow < bi)) { best = score; bi = myrow; bl = myl; }
                lsmerge(lm, ls, myl, 1.f);
            }
        }
#pragma unroll
        for (int o = 16; o; o >>= 1) {
            float ob = __shfl_xor_sync(~0u, best, o);
            int oi = __shfl_xor_sync(~0u, bi, o);
            float ol = __shfl_xor_sync(~0u, bl, o);
            if (ob > best || (ob == best && oi < bi)) { best = ob; bi = oi; bl = ol; }
            float om = __shfl_xor_sync(~0u, lm, o);
            float os = __shfl_xor_sync(~0u, ls, o);
            lsmerge(lm, ls, om, os);
        }
        if (lane == 0) { wbest[w] = best; wbi[w] = bi; wbl[w] = bl; wlm[w] = lm; wls[w] = ls; }
        __syncthreads();
        if (t == 0) {
            float B = NI, BL = 0.f; int BI = 0x7fffffff; float M = NI, S = 0.f;
            for (int i = 0; i < 8; i++) {
                if (wbest[i] > B || (wbest[i] == B && wbi[i] < BI)) { B = wbest[i]; BI = wbi[i]; BL = wbl[i]; }
                lsmerge(M, S, wlm[i], wls[i]);
            }
            d_pm_best[wp][blockIdx.x] = B; d_pm_bi[wp][blockIdx.x] = BI; d_pm_bl[wp][blockIdx.x] = BL;
            d_pm_lm[wp][blockIdx.x] = M;  d_pm_ls[wp][blockIdx.x] = S;
            __threadfence();
            atomicAdd(&d_arr[step], 1);
        }
        __syncthreads();
    }

    // ---- final sample (block 0) ----
    if (blockIdx.x == 0) {
        if (t == 0) { while (atomicAdd(&d_arr[HOR - 1], 0) < GLOG) __nanosleep(32); }
        __syncthreads();
        __threadfence();
        if (t < 32) {
            int pb = (HOR - 1) & 1;
            float B = NI, BL = 0.f; int BI = 0x7fffffff; float M = NI, S = 0.f;
            for (int i = lane; i < GLOG; i += 32) {
                float b = d_pm_best[pb][i]; int bidx = d_pm_bi[pb][i];
                if (b > B || (b == B && bidx < BI)) { B = b; BI = bidx; BL = d_pm_bl[pb][i]; }
                lsmerge(M, S, d_pm_lm[pb][i], d_pm_ls[pb][i]);
            }
#pragma unroll
            for (int o = 16; o; o >>= 1) {
                float ob = __shfl_xor_sync(~0u, B, o);
                int oi = __shfl_xor_sync(~0u, BI, o);
                float ol = __shfl_xor_sync(~0u, BL, o);
                if (ob > B || (ob == B && oi < BI)) { B = ob; BI = oi; BL = ol; }
                float om = __shfl_xor_sync(~0u, M, o);
                float os = __shfl_xor_sync(~0u, S, o);
                lsmerge(M, S, om, os);
            }
            if (lane == 0) {
                out[HOR - 1] = (float)BI;
                out[2 * HOR - 1] = BL - (M + logf(S));
            }
        }
    }
}

// ---------------- launch ----------------
extern "C" void kernel_launch(void* const* d_in, const int* in_sizes, int n_in,
                              void* d_out, int out_size) {
    const float* state_features = (const float*)d_in[0];
    const float* model_features = (const float*)d_in[1];
    const void*  edge_index     = d_in[2];
    const float* W_l   = (const float*)d_in[3];
    const float* W_r   = (const float*)d_in[4];
    const float* att   = (const float*)d_in[5];
    const float* cbias = (const float*)d_in[6];
    const float* Wih   = (const float*)d_in[7];
    const float* Whh   = (const float*)d_in[8];
    const float* bih   = (const float*)d_in[9];
    const float* bhh   = (const float*)d_in[10];
    const float* W1    = (const float*)d_in[11];
    const float* b1    = (const float*)d_in[12];
    const float* W2    = (const float*)d_in[13];
    const float* b2    = (const float*)d_in[14];
    const float* emb   = (const float*)d_in[15];
    float* out = (float*)d_out;

    const int smemB = 2 * SM_GB * (int)sizeof(uint32_t);  // 69632
    cudaFuncSetAttribute(k_gemm_mma, cudaFuncAttributeMaxDynamicSharedMemorySize, smemB);

    float* xl; float* xr;
    cudaGetSymbolAddress((void**)&xl, d_xl);
    cudaGetSymbolAddress((void**)&xr, d_xr);
    uint32_t *whl, *wll, *whr, *wlr;
    cudaGetSymbolAddress((void**)&whl, d_wphl);
    cudaGetSymbolAddress((void**)&wll, d_wpll);
    cudaGetSymbolAddress((void**)&whr, d_wphr);
    cudaGetSymbolAddress((void**)&wlr, d_wplr);

    k_init<<<(NSN + 255) / 256, 256>>>(edge_index);
    k_wconv<<<32, 256>>>(W_l, W_r);
    k_gemm_mma<<<(NMD + 127) / 128, 256, smemB>>>(model_features, whr, wlr, xr, NMD);
    k_gemm_mma<<<(NSN + 127) / 128, 256, smemB>>>(state_features, whl, wll, xl, NSN);  // profiled
    k_lstmT<<<128, 256>>>(Wih, Whh);
    k_edge12<<<1184, 256>>>(edge_index, att);
    k_edge3a<<<(EE + 255) / 256, 256>>>(edge_index);
    k_dense<<<296, 256>>>();
    k_fing<<<1, 128>>>(cbias);
    k_rollall<<<GLOG, 256>>>(bih, bhh, W1, b1, W2, b2, emb, out);
    (void)in_sizes; (void)n_in; (void)out_size;
}

// round 14
// speedup vs baseline: 1.0701x; 1.0701x over previous
#include <cuda_runtime.h>
#include <cuda_bf16.h>
#include <cstdint>
#include <cstddef>

#define NSN  100000
#define NMD  50000
#define EE   600000
#define D    128
#define HOR  8
#define NEG  0.2f
#define GLOG 128        // rollout blocks (<= SM count: all co-resident)
#define RPB  391        // rows per block: 128*391 >= 50000
#define RSTRIDE 129     // odd word stride -> conflict-free per-lane-row LDS

// ---------------- device scratch ----------------
__device__ float    d_xl[(size_t)NSN * D];
__device__ float    d_xr[(size_t)NMD * D];
__device__ float    d_ew[EE];
__device__ float    d_ssum[NMD];
__device__ float    d_csrc[NSN];
__device__ __align__(16) float d_gacc[D];
__device__ __align__(16) float d_inp[D];
__device__ __align__(16) float d_h[D];
__device__ __align__(16) float d_c[D];
__device__ __align__(16) float d_h2g[D];
__device__ float    d_pm_best[2][GLOG];
__device__ int      d_pm_bi[2][GLOG];
__device__ float    d_pm_bl[2][GLOG];
__device__ float    d_pm_lm[2][GLOG];
__device__ float    d_pm_ls[2][GLOG];
__device__ uint2    d_keys[HOR];
__device__ int      d_is64;
__device__ int      d_ready[HOR];
__device__ int      d_arr[HOR];
#define WSTRIDE 136
__device__ __align__(16) uint32_t d_wphl[64 * WSTRIDE];
__device__ __align__(16) uint32_t d_wpll[64 * WSTRIDE];
__device__ __align__(16) uint32_t d_wphr[64 * WSTRIDE];
__device__ __align__(16) uint32_t d_wplr[64 * WSTRIDE];
// LSTM weights packed: d_wpih[k2*256+t] = (Wih[2t][2k2],Wih[2t][2k2+1],Wih[2t+1][2k2],Wih[2t+1][2k2+1])
__device__ __align__(16) float4 d_wpih[64 * 256];
__device__ __align__(16) float4 d_wphh[64 * 256];

// ---------------- helpers ----------------
__device__ __forceinline__ int eidx(const void* ei, int is64, long long pos) {
    return is64 ? (int)((const long long*)ei)[pos] : ((const int*)ei)[pos];
}
__device__ __forceinline__ float neginf() { return __int_as_float((int)0xff800000); }

__device__ __forceinline__ uint2 tf2x32(unsigned k0, unsigned k1, unsigned x0, unsigned x1) {
    unsigned k2 = k0 ^ k1 ^ 0x1BD11BDAu;
    x0 += k0; x1 += k1;
#define TFR(r) { x0 += x1; x1 = (x1 << (r)) | (x1 >> (32 - (r))); x1 ^= x0; }
    TFR(13) TFR(15) TFR(26) TFR(6)   x0 += k1; x1 += k2 + 1u;
    TFR(17) TFR(29) TFR(16) TFR(24)  x0 += k2; x1 += k0 + 2u;
    TFR(13) TFR(15) TFR(26) TFR(6)   x0 += k0; x1 += k1 + 3u;
    TFR(17) TFR(29) TFR(16) TFR(24)  x0 += k1; x1 += k2 + 4u;
    TFR(13) TFR(15) TFR(26) TFR(6)   x0 += k2; x1 += k0 + 5u;
#undef TFR
    return make_uint2(x0, x1);
}

__device__ __forceinline__ void lsmerge(float& M, float& S, float m, float s) {
    if (s > 0.f) {
        if (m > M) { S = S * expf(M - m) + s; M = m; }
        else       { S += s * expf(m - M); }
    }
}

__device__ __forceinline__ void mma_bf16(float* c, const uint32_t* a, uint32_t b0, uint32_t b1) {
    asm volatile(
        "mma.sync.aligned.m16n8k16.row.col.f32.bf16.bf16.f32 "
        "{%0,%1,%2,%3}, {%4,%5,%6,%7}, {%8,%9}, {%0,%1,%2,%3};"
        : "+f"(c[0]), "+f"(c[1]), "+f"(c[2]), "+f"(c[3])
        : "r"(a[0]), "r"(a[1]), "r"(a[2]), "r"(a[3]), "r"(b0), "r"(b1));
}

__device__ __forceinline__ uint32_t pack_hi(float e, float o) {
    unsigned a = __bfloat16_as_ushort(__float2bfloat16_rn(e));
    unsigned b = __bfloat16_as_ushort(__float2bfloat16_rn(o));
    return a | (b << 16);
}
__device__ __forceinline__ uint32_t pack_lo(float e, float o) {
    float he = __bfloat162float(__float2bfloat16_rn(e));
    float ho = __bfloat162float(__float2bfloat16_rn(o));
    unsigned a = __bfloat16_as_ushort(__float2bfloat16_rn(e - he));
    unsigned b = __bfloat16_as_ushort(__float2bfloat16_rn(o - ho));
    return a | (b << 16);
}

// ---------------- init ----------------
__global__ void k_init(const void* ei) {
    int i = blockIdx.x * blockDim.x + threadIdx.x;
    if (i < NMD) d_ssum[i] = 0.f;
    if (i < NSN) d_csrc[i] = 0.f;
    if (i < D) { d_gacc[i] = 0.f; d_h[i] = 0.f; d_c[i] = 0.f; }
    if (i < HOR) { d_ready[i] = 0; d_arr[i] = 0; }
    if (i == 0) {
        const int* p = (const int*)ei;
        int all0 = 1;
        for (int j = 1; j < 201; j += 2) all0 &= (p[j] == 0);
        d_is64 = all0;
        for (int j = 0; j < HOR; j++) {
            uint2 r = tf2x32(0u, 42u, 0u, (unsigned)j);
            d_keys[j] = make_uint2(r.x, r.y);
        }
    }
}

// ---------------- W [n][k] -> packed bf16 hi/lo [kp][n] (stride 136) ----------------
__global__ void k_wconv(const float* __restrict__ Wl, const float* __restrict__ Wr) {
    int idx = blockIdx.x * blockDim.x + threadIdx.x;
    if (idx >= 64 * 128) return;
    int kp = idx >> 7, n = idx & 127;
    int o = kp * WSTRIDE + n;
    float le = Wl[n * D + 2 * kp], lo = Wl[n * D + 2 * kp + 1];
    d_wphl[o] = pack_hi(le, lo);
    d_wpll[o] = pack_lo(le, lo);
    float re = Wr[n * D + 2 * kp], ro = Wr[n * D + 2 * kp + 1];
    d_wphr[o] = pack_hi(re, ro);
    d_wplr[o] = pack_lo(re, ro);
}

// ---------------- repack LSTM weights to float4 k-pairs ----------------
__global__ void k_lstmT4(const float* __restrict__ Wih, const float* __restrict__ Whh) {
    int idx = blockIdx.x * blockDim.x + threadIdx.x;   // 64*256
    if (idx >= 64 * 256) return;
    int k2 = idx >> 8, t = idx & 255;
    d_wpih[idx] = make_float4(Wih[(2 * t) * D + 2 * k2], Wih[(2 * t) * D + 2 * k2 + 1],
                              Wih[(2 * t + 1) * D + 2 * k2], Wih[(2 * t + 1) * D + 2 * k2 + 1]);
    d_wphh[idx] = make_float4(Whh[(2 * t) * D + 2 * k2], Whh[(2 * t) * D + 2 * k2 + 1],
                              Whh[(2 * t + 1) * D + 2 * k2], Whh[(2 * t + 1) * D + 2 * k2 + 1]);
}

// ---------------- HMMA GEMM ----------------
#define SM_GB (64 * WSTRIDE)
__global__ void __launch_bounds__(256, 2) k_gemm_mma(const float* __restrict__ X,
                                                     const uint32_t* __restrict__ gbh,
                                                     const uint32_t* __restrict__ gbl,
                                                     float* __restrict__ Y, int rows) {
    extern __shared__ uint32_t bs[];
    uint32_t* Bh = bs;
    uint32_t* Bl = bs + SM_GB;
    for (int i = threadIdx.x; i < SM_GB / 4; i += 256) {
        ((uint4*)Bh)[i] = ((const uint4*)gbh)[i];
        ((uint4*)Bl)[i] = ((const uint4*)gbl)[i];
    }
    __syncthreads();
    int w = threadIdx.x >> 5, lane = threadIdx.x & 31;
    int q = lane & 3, g = lane >> 2;
    int r0 = blockIdx.x * 128 + w * 16 + g;
    const float* x0 = X + (size_t)(r0 < rows ? r0 : rows - 1) * D;
    const float* x1 = X + (size_t)(r0 + 8 < rows ? r0 + 8 : rows - 1) * D;
    float acc[16][4];
#pragma unroll
    for (int nt = 0; nt < 16; nt++) { acc[nt][0] = acc[nt][1] = acc[nt][2] = acc[nt][3] = 0.f; }
#pragma unroll
    for (int k8 = 0; k8 < 8; k8++) {
        int c0 = k8 * 16 + 2 * q;
        float2 p0 = *(const float2*)(x0 + c0);
        float2 p1 = *(const float2*)(x1 + c0);
        float2 p2 = *(const float2*)(x0 + c0 + 8);
        float2 p3 = *(const float2*)(x1 + c0 + 8);
        uint32_t ah[4], al[4];
        ah[0] = pack_hi(p0.x, p0.y); al[0] = pack_lo(p0.x, p0.y);
        ah[1] = pack_hi(p1.x, p1.y); al[1] = pack_lo(p1.x, p1.y);
        ah[2] = pack_hi(p2.x, p2.y); al[2] = pack_lo(p2.x, p2.y);
        ah[3] = pack_hi(p3.x, p3.y); al[3] = pack_lo(p3.x, p3.y);
        int kb0 = (k8 * 8 + q) * WSTRIDE + g;
        int kb1 = (k8 * 8 + q + 4) * WSTRIDE + g;
#pragma unroll
        for (int nt = 0; nt < 16; nt++) {
            uint32_t bh0 = Bh[kb0 + nt * 8];
            uint32_t bh1 = Bh[kb1 + nt * 8];
            uint32_t bl0 = Bl[kb0 + nt * 8];
            uint32_t bl1 = Bl[kb1 + nt * 8];
            mma_bf16(acc[nt], ah, bh0, bh1);
            mma_bf16(acc[nt], ah, bl0, bl1);
            mma_bf16(acc[nt], al, bh0, bh1);
        }
    }
    bool w0 = r0 < rows, w1 = (r0 + 8) < rows;
#pragma unroll
    for (int nt = 0; nt < 16; nt++) {
        int col = nt * 8 + 2 * q;
        if (w0) *(float2*)(Y + (size_t)r0 * D + col) = make_float2(acc[nt][0], acc[nt][1]);
        if (w1) *(float2*)(Y + (size_t)(r0 + 8) * D + col) = make_float2(acc[nt][2], acc[nt][3]);
    }
}

// ---------------- fused edge pass ----------------
__global__ void __launch_bounds__(256) k_edge12(const void* __restrict__ ei,
                                                const float* __restrict__ att) {
    int lane = threadIdx.x & 31;
    int wid = (blockIdx.x * blockDim.x + threadIdx.x) >> 5;
    int nw = (gridDim.x * blockDim.x) >> 5;
    int is64 = d_is64;
    float4 av = ((const float4*)att)[lane];
    for (int e = wid * 2; e < EE; e += nw * 2) {
        int s1 = eidx(ei, is64, e);
        int dd1 = eidx(ei, is64, (long long)EE + e);
        int s2 = eidx(ei, is64, e + 1);
        int dd2 = eidx(ei, is64, (long long)EE + e + 1);
        float4 l1 = ((const float4*)(d_xl + (size_t)s1 * D))[lane];
        float4 r1 = ((const float4*)(d_xr + (size_t)dd1 * D))[lane];
        float4 l2 = ((const float4*)(d_xl + (size_t)s2 * D))[lane];
        float4 r2 = ((const float4*)(d_xr + (size_t)dd2 * D))[lane];
        float zx, zy, zz, zw, p1, p2;
        zx = l1.x + r1.x; zy = l1.y + r1.y; zz = l1.z + r1.z; zw = l1.w + r1.w;
        zx = zx > 0.f ? zx : NEG * zx; zy = zy > 0.f ? zy : NEG * zy;
        zz = zz > 0.f ? zz : NEG * zz; zw = zw > 0.f ? zw : NEG * zw;
        p1 = av.x * zx + av.y * zy + av.z * zz + av.w * zw;
        zx = l2.x + r2.x; zy = l2.y + r2.y; zz = l2.z + r2.z; zw = l2.w + r2.w;
        zx = zx > 0.f ? zx : NEG * zx; zy = zy > 0.f ? zy : NEG * zy;
        zz = zz > 0.f ? zz : NEG * zz; zw = zw > 0.f ? zw : NEG * zw;
        p2 = av.x * zx + av.y * zy + av.z * zz + av.w * zw;
#pragma unroll
        for (int o = 16; o; o >>= 1) {
            p1 += __shfl_xor_sync(~0u, p1, o);
            p2 += __shfl_xor_sync(~0u, p2, o);
        }
        if (lane == 0) {
            float e1 = expf(p1), e2 = expf(p2);
            d_ew[e] = e1;     atomicAdd(&d_ssum[dd1], e1);
            d_ew[e + 1] = e2; atomicAdd(&d_ssum[dd2], e2);
        }
    }
}

__global__ void k_edge3a(const void* __restrict__ ei) {
    int i = blockIdx.x * blockDim.x + threadIdx.x;
    if (i >= EE) return;
    int is64 = d_is64;
    int src = eidx(ei, is64, i);
    int dst = eidx(ei, is64, (long long)EE + i);
    atomicAdd(&d_csrc[src], d_ew[i] / d_ssum[dst]);
}

__global__ void __launch_bounds__(256) k_dense() {
    __shared__ float sg[D];
    int lane = threadIdx.x & 31, w = threadIdx.x >> 5;
    if (threadIdx.x < D) sg[threadIdx.x] = 0.f;
    __syncthreads();
    int gw = blockIdx.x * 8 + w;
    int nw = gridDim.x * 8;
    float4 acc = make_float4(0.f, 0.f, 0.f, 0.f);
    for (int r = gw; r < NSN; r += nw) {
        float cv = d_csrc[r];
        float4 v = ((const float4*)(d_xl + (size_t)r * D))[lane];
        acc.x += cv * v.x; acc.y += cv * v.y; acc.z += cv * v.z; acc.w += cv * v.w;
    }
    atomicAdd(&sg[lane * 4 + 0], acc.x);
    atomicAdd(&sg[lane * 4 + 1], acc.y);
    atomicAdd(&sg[lane * 4 + 2], acc.z);
    atomicAdd(&sg[lane * 4 + 3], acc.w);
    __syncthreads();
    if (threadIdx.x < D) atomicAdd(&d_gacc[threadIdx.x], sg[threadIdx.x]);
}

__global__ void k_fing(const float* __restrict__ conv_bias) {
    int t = threadIdx.x;
    if (t < D) d_inp[t] = d_gacc[t] * (1.0f / (float)NMD) + conv_bias[t];
}

// ---------------- fused 8-step rollout, W2 slice cached in SMEM ----------------
__global__ void __launch_bounds__(256) k_rollall(
    const float* __restrict__ bih, const float* __restrict__ bhh,
    const float* __restrict__ W1,  const float* __restrict__ b1,
    const float* __restrict__ W2,  const float* __restrict__ b2,
    const float* __restrict__ emb, float* __restrict__ out) {
    extern __shared__ float w2s[];   // [RPB][RSTRIDE] row-major, odd stride
    __shared__ float si[D], sh[D], sg[4 * D], snh[D], sh2[D];
    __shared__ float wbest[8], wbl[8], wlm[8], wls[8];
    __shared__ int wbi[8], sAct;
    int t = threadIdx.x, lane = t & 31, w = t >> 5;
    const float NI = neginf();

    int r0 = blockIdx.x * RPB;
    int R = NMD - r0; if (R > RPB) R = RPB;

    // stage this block's W2 slice into smem (coalesced LDG.128, 4x STS.32)
    for (int idx = t; idx < R * 32; idx += 256) {
        int rloc = idx >> 5, c4 = idx & 31;
        float4 v = ((const float4*)(W2 + (size_t)(r0 + rloc) * D))[c4];
        float* dstp = w2s + rloc * RSTRIDE + c4 * 4;
        dstp[0] = v.x; dstp[1] = v.y; dstp[2] = v.z; dstp[3] = v.w;
    }
    __syncthreads();

    for (int step = 0; step < HOR; step++) {
        int wp = step & 1, pmr = (step - 1) & 1;
        if (blockIdx.x == 0) {
            if (step > 0) {
                if (t == 0) {
                    while (*(volatile int*)&d_arr[step - 1] < GLOG) __nanosleep(64);
                }
                __syncthreads();
                __threadfence();
                if (t < 32) {
                    float B = NI, BL = 0.f; int BI = 0x7fffffff; float M = NI, S = 0.f;
                    for (int i = lane; i < GLOG; i += 32) {
                        float b = d_pm_best[pmr][i]; int bidx = d_pm_bi[pmr][i];
                        if (b > B || (b == B && bidx < BI)) { B = b; BI = bidx; BL = d_pm_bl[pmr][i]; }
                        lsmerge(M, S, d_pm_lm[pmr][i], d_pm_ls[pmr][i]);
                    }
#pragma unroll
                    for (int o = 16; o; o >>= 1) {
                        float ob = __shfl_xor_sync(~0u, B, o);
                        int oi = __shfl_xor_sync(~0u, BI, o);
                        float ol = __shfl_xor_sync(~0u, BL, o);
                        if (ob > B || (ob == B && oi < BI)) { B = ob; BI = oi; BL = ol; }
                        float om = __shfl_xor_sync(~0u, M, o);
                        float os = __shfl_xor_sync(~0u, S, o);
                        lsmerge(M, S, om, os);
                    }
                    if (lane == 0) {
                        out[step - 1] = (float)BI;
                        out[HOR + step - 1] = BL - (M + logf(S));
                        sAct = BI;
                    }
                }
                __syncthreads();
                if (t < D) si[t] = emb[(size_t)sAct * D + t];
            } else {
                if (t < D) si[t] = d_inp[t];
            }
            if (t < D) sh[t] = d_h[t];
            __syncthreads();
            // LSTM gates: thread t -> rows 2t, 2t+1 via float4 k-pairs
            {
                float2 bi_ = ((const float2*)bih)[t];
                float2 bh_ = ((const float2*)bhh)[t];
                float ax = bi_.x + bh_.x, ay = bi_.y + bh_.y;
#pragma unroll 4
                for (int k2 = 0; k2 < 64; k2++) {
                    float4 wi = d_wpih[k2 * 256 + t];
                    float4 wh = d_wphh[k2 * 256 + t];
                    float x0 = si[2 * k2], x1 = si[2 * k2 + 1];
                    float h0 = sh[2 * k2], h1 = sh[2 * k2 + 1];
                    ax += wi.x * x0 + wi.y * x1 + wh.x * h0 + wh.y * h1;
                    ay += wi.z * x0 + wi.w * x1 + wh.z * h0 + wh.w * h1;
                }
                sg[2 * t] = ax; sg[2 * t + 1] = ay;
            }
            __syncthreads();
            if (t < D) {
                float ig = 1.f / (1.f + expf(-sg[t]));
                float fg = 1.f / (1.f + expf(-sg[D + t]));
                float gg = tanhf(sg[2 * D + t]);
                float og = 1.f / (1.f + expf(-sg[3 * D + t]));
                float c = fg * d_c[t] + ig * gg;
                float h = og * tanhf(c);
                snh[t] = h;
                d_c[t] = c; d_h[t] = h;
                if (step == HOR - 1) { out[2 * HOR + t] = h; out[2 * HOR + D + t] = c; }
            }
            __syncthreads();
            if (t < D) {
                float a0 = b1[t], a1 = 0.f;
                const float4* w1 = (const float4*)(W1 + (size_t)t * D);
#pragma unroll 8
                for (int k = 0; k < 32; k += 2) {
                    float4 a = w1[k];     float4 hv = *(const float4*)(snh + 4 * k);
                    float4 b = w1[k + 1]; float4 h2v = *(const float4*)(snh + 4 * k + 4);
                    a0 += a.x * hv.x + a.y * hv.y + a.z * hv.z + a.w * hv.w;
                    a1 += b.x * h2v.x + b.y * h2v.y + b.z * h2v.z + b.w * h2v.w;
                }
                float a2 = a0 + a1;
                a2 = a2 > 0.f ? a2 : 0.f;
                sh2[t] = a2;
                d_h2g[t] = a2;
            }
            __syncthreads();
            if (t == 0) { __threadfence(); *(volatile int*)&d_ready[step] = 1; }
        } else {
            if (t == 0) {
                while (*(volatile int*)&d_ready[step] == 0) __nanosleep(64);
            }
            __syncthreads();
            __threadfence();
            if (t < D) sh2[t] = __ldcg(&d_h2g[t]);
            __syncthreads();
        }

        // ---- phase B: per-lane-row logits from SMEM + gumbel + online softmax ----
        uint2 key = d_keys[step];
        float best = NI, bl = 0.f; int bi = 0x7fffffff;
        float lm = NI, ls = 0.f;
        for (int base = w * 32; base < R; base += 256) {
            int rl = base + lane;
            float myl = 0.f;
            if (rl < R) {
                const float* wrow = w2s + rl * RSTRIDE;
                float a0 = 0.f, a1 = 0.f, a2 = 0.f, a3 = 0.f;
#pragma unroll 8
                for (int c4 = 0; c4 < 32; c4++) {
                    float4 h = ((const float4*)sh2)[c4];
                    a0 += wrow[4 * c4 + 0] * h.x;
                    a1 += wrow[4 * c4 + 1] * h.y;
                    a2 += wrow[4 * c4 + 2] * h.z;
                    a3 += wrow[4 * c4 + 3] * h.w;
                }
                int myrow = r0 + rl;
                myl = (a0 + a1) + (a2 + a3) + b2[myrow];
                uint2 tr = tf2x32(key.x, key.y, 0u, (unsigned)myrow);
                unsigned bits = tr.x ^ tr.y;
                float u = __uint_as_float((bits >> 9) | 0x3f800000u) - 1.0f;
                if (u == 0.f) u = 1.17549435e-38f;
                float score = myl - logf(-logf(u));
                if (score > best || (score == best && myrow < bi)) { best = score; bi = myrow; bl = myl; }
                lsmerge(lm, ls, myl, 1.f);
            }
        }
#pragma unroll
        for (int o = 16; o; o >>= 1) {
            float ob = __shfl_xor_sync(~0u, best, o);
            int oi = __shfl_xor_sync(~0u, bi, o);
            float ol = __shfl_xor_sync(~0u, bl, o);
            if (ob > best || (ob == best && oi < bi)) { best = ob; bi = oi; bl = ol; }
            float om = __shfl_xor_sync(~0u, lm, o);
            float os = __shfl_xor_sync(~0u, ls, o);
            lsmerge(lm, ls, om, os);
        }
        if (lane == 0) { wbest[w] = best; wbi[w] = bi; wbl[w] = bl; wlm[w] = lm; wls[w] = ls; }
        __syncthreads();
        if (t == 0) {
            float B = NI, BL = 0.f; int BI = 0x7fffffff; float M = NI, S = 0.f;
            for (int i = 0; i < 8; i++) {
                if (wbest[i] > B || (wbest[i] == B && wbi[i] < BI)) { B = wbest[i]; BI = wbi[i]; BL = wbl[i]; }
                lsmerge(M, S, wlm[i], wls[i]);
            }
            d_pm_best[wp][blockIdx.x] = B; d_pm_bi[wp][blockIdx.x] = BI; d_pm_bl[wp][blockIdx.x] = BL;
            d_pm_lm[wp][blockIdx.x] = M;  d_pm_ls[wp][blockIdx.x] = S;
            __threadfence();
            atomicAdd(&d_arr[step], 1);
        }
        __syncthreads();
    }

    // ---- final sample (block 0) ----
    if (blockIdx.x == 0) {
        if (t == 0) { while (*(volatile int*)&d_arr[HOR - 1] < GLOG) __nanosleep(64); }
        __syncthreads();
        __threadfence();
        if (t < 32) {
            int pb = (HOR - 1) & 1;
            float B = NI, BL = 0.f; int BI = 0x7fffffff; float M = NI, S = 0.f;
            for (int i = lane; i < GLOG; i += 32) {
                float b = d_pm_best[pb][i]; int bidx = d_pm_bi[pb][i];
                if (b > B || (b == B && bidx < BI)) { B = b; BI = bidx; BL = d_pm_bl[pb][i]; }
                lsmerge(M, S, d_pm_lm[pb][i], d_pm_ls[pb][i]);
            }
#pragma unroll
            for (int o = 16; o; o >>= 1) {
                float ob = __shfl_xor_sync(~0u, B, o);
                int oi = __shfl_xor_sync(~0u, BI, o);
                float ol = __shfl_xor_sync(~0u, BL, o);
                if (ob > B || (ob == B && oi < BI)) { B = ob; BI = oi; BL = ol; }
                float om = __shfl_xor_sync(~0u, M, o);
                float os = __shfl_xor_sync(~0u, S, o);
                lsmerge(M, S, om, os);
            }
            if (lane == 0) {
                out[HOR - 1] = (float)BI;
                out[2 * HOR - 1] = BL - (M + logf(S));
            }
        }
    }
}

// ---------------- launch ----------------
extern "C" void kernel_launch(void* const* d_in, const int* in_sizes, int n_in,
                              void* d_out, int out_size) {
    const float* state_features = (const float*)d_in[0];
    const float* model_features = (const float*)d_in[1];
    const void*  edge_index     = d_in[2];
    const float* W_l   = (const float*)d_in[3];
    const float* W_r   = (const float*)d_in[4];
    const float* att   = (const float*)d_in[5];
    const float* cbias = (const float*)d_in[6];
    const float* Wih   = (const float*)d_in[7];
    const float* Whh   = (const float*)d_in[8];
    const float* bih   = (const float*)d_in[9];
    const float* bhh   = (const float*)d_in[10];
    const float* W1    = (const float*)d_in[11];
    const float* b1    = (const float*)d_in[12];
    const float* W2    = (const float*)d_in[13];
    const float* b2    = (const float*)d_in[14];
    const float* emb   = (const float*)d_in[15];
    float* out = (float*)d_out;

    const int smemB = 2 * SM_GB * (int)sizeof(uint32_t);        // 69632
    const int smemR = RPB * RSTRIDE * (int)sizeof(float);       // 201,756
    cudaFuncSetAttribute(k_gemm_mma, cudaFuncAttributeMaxDynamicSharedMemorySize, smemB);
    cudaFuncSetAttribute(k_rollall, cudaFuncAttributeMaxDynamicSharedMemorySize, smemR);

    float* xl; float* xr;
    cudaGetSymbolAddress((void**)&xl, d_xl);
    cudaGetSymbolAddress((void**)&xr, d_xr);
    uint32_t *whl, *wll, *whr, *wlr;
    cudaGetSymbolAddress((void**)&whl, d_wphl);
    cudaGetSymbolAddress((void**)&wll, d_wpll);
    cudaGetSymbolAddress((void**)&whr, d_wphr);
    cudaGetSymbolAddress((void**)&wlr, d_wplr);

    k_init<<<(NSN + 255) / 256, 256>>>(edge_index);
    k_wconv<<<32, 256>>>(W_l, W_r);
    k_gemm_mma<<<(NMD + 127) / 128, 256, smemB>>>(model_features, whr, wlr, xr, NMD);
    k_gemm_mma<<<(NSN + 127) / 128, 256, smemB>>>(state_features, whl, wll, xl, NSN);  // profiled
    k_lstmT4<<<64, 256>>>(Wih, Whh);
    k_edge12<<<1184, 256>>>(edge_index, att);
    k_edge3a<<<(EE + 255) / 256, 256>>>(edge_index);
    k_dense<<<296, 256>>>();
    k_fing<<<1, 128>>>(cbias);
    k_rollall<<<GLOG, 256, smemR>>>(bih, bhh, W1, b1, W2, b2, emb, out);
    (void)in_sizes; (void)n_in; (void)out_size;
}

// round 15
// speedup vs baseline: 1.0849x; 1.0138x over previous
#include <cuda_runtime.h>
#include <cuda_bf16.h>
#include <cstdint>
#include <cstddef>

#define NSN  100000
#define NMD  50000
#define EE   600000
#define D    128
#define HOR  8
#define NEG  0.2f
#define GLOG 128        // rollout blocks (1/SM at 201KB smem -> co-resident)
#define RPB  391        // W2 rows per block
#define RSTRIDE 129     // odd word stride -> conflict-free per-lane-row LDS

// ---------------- device scratch ----------------
__device__ float    d_xl[(size_t)NSN * D];
__device__ float    d_xr[(size_t)NMD * D];
__device__ float    d_ew[EE];
__device__ float    d_ssum[NMD];
__device__ float    d_csrc[NSN];
__device__ __align__(16) float d_gacc[D];
__device__ __align__(16) float d_h[D];
__device__ __align__(16) float d_c[D];
__device__ __align__(16) float d_h2g[D];
__device__ float    d_pm_best[2][GLOG];
__device__ int      d_pm_bi[2][GLOG];
__device__ float    d_pm_bl[2][GLOG];
__device__ float    d_pm_lm[2][GLOG];
__device__ float    d_pm_ls[2][GLOG];
__device__ uint2    d_keys[HOR];
__device__ int      d_is64;
__device__ int      d_ready[HOR];
__device__ int      d_arr[HOR];
__device__ volatile unsigned d_bgen;
__device__ unsigned d_bcnt;
#define WSTRIDE 136
__device__ __align__(16) uint32_t d_wphl[64 * WSTRIDE];
__device__ __align__(16) uint32_t d_wpll[64 * WSTRIDE];
__device__ __align__(16) uint32_t d_wphr[64 * WSTRIDE];
__device__ __align__(16) uint32_t d_wplr[64 * WSTRIDE];
__device__ __align__(16) float4 d_wpih[64 * 256];
__device__ __align__(16) float4 d_wphh[64 * 256];

// ---------------- helpers ----------------
__device__ __forceinline__ int eidx(const void* ei, int is64, long long pos) {
    return is64 ? (int)((const long long*)ei)[pos] : ((const int*)ei)[pos];
}
__device__ __forceinline__ float neginf() { return __int_as_float((int)0xff800000); }

__device__ __forceinline__ uint2 tf2x32(unsigned k0, unsigned k1, unsigned x0, unsigned x1) {
    unsigned k2 = k0 ^ k1 ^ 0x1BD11BDAu;
    x0 += k0; x1 += k1;
#define TFR(r) { x0 += x1; x1 = (x1 << (r)) | (x1 >> (32 - (r))); x1 ^= x0; }
    TFR(13) TFR(15) TFR(26) TFR(6)   x0 += k1; x1 += k2 + 1u;
    TFR(17) TFR(29) TFR(16) TFR(24)  x0 += k2; x1 += k0 + 2u;
    TFR(13) TFR(15) TFR(26) TFR(6)   x0 += k0; x1 += k1 + 3u;
    TFR(17) TFR(29) TFR(16) TFR(24)  x0 += k1; x1 += k2 + 4u;
    TFR(13) TFR(15) TFR(26) TFR(6)   x0 += k2; x1 += k0 + 5u;
#undef TFR
    return make_uint2(x0, x1);
}

__device__ __forceinline__ void lsmerge(float& M, float& S, float m, float s) {
    if (s > 0.f) {
        if (m > M) { S = S * expf(M - m) + s; M = m; }
        else       { S += s * expf(m - M); }
    }
}

__device__ __forceinline__ void mma_bf16(float* c, const uint32_t* a, uint32_t b0, uint32_t b1) {
    asm volatile(
        "mma.sync.aligned.m16n8k16.row.col.f32.bf16.bf16.f32 "
        "{%0,%1,%2,%3}, {%4,%5,%6,%7}, {%8,%9}, {%0,%1,%2,%3};"
        : "+f"(c[0]), "+f"(c[1]), "+f"(c[2]), "+f"(c[3])
        : "r"(a[0]), "r"(a[1]), "r"(a[2]), "r"(a[3]), "r"(b0), "r"(b1));
}

__device__ __forceinline__ uint32_t pack_hi(float e, float o) {
    unsigned a = __bfloat16_as_ushort(__float2bfloat16_rn(e));
    unsigned b = __bfloat16_as_ushort(__float2bfloat16_rn(o));
    return a | (b << 16);
}
__device__ __forceinline__ uint32_t pack_lo(float e, float o) {
    float he = __bfloat162float(__float2bfloat16_rn(e));
    float ho = __bfloat162float(__float2bfloat16_rn(o));
    unsigned a = __bfloat16_as_ushort(__float2bfloat16_rn(e - he));
    unsigned b = __bfloat16_as_ushort(__float2bfloat16_rn(o - ho));
    return a | (b << 16);
}

// grid barrier for the 128 co-resident rollall blocks
__device__ __forceinline__ void gridbar128() {
    __syncthreads();
    if (threadIdx.x == 0) {
        __threadfence();
        unsigned gen = d_bgen;
        if (atomicAdd(&d_bcnt, 1u) == GLOG - 1) {
            d_bcnt = 0;
            __threadfence();
            d_bgen = gen + 1u;
        } else {
            while (d_bgen == gen) __nanosleep(64);
        }
        __threadfence();
    }
    __syncthreads();
}

// ---------------- prep: init + W pack + LSTM repack ----------------
__global__ void k_prep(const void* ei, const float* __restrict__ Wl,
                       const float* __restrict__ Wr, const float* __restrict__ Wih,
                       const float* __restrict__ Whh) {
    int i = blockIdx.x * blockDim.x + threadIdx.x;
    if (i < NMD) d_ssum[i] = 0.f;
    if (i < NSN) d_csrc[i] = 0.f;
    if (i < D) { d_gacc[i] = 0.f; d_h[i] = 0.f; d_c[i] = 0.f; }
    if (i < HOR) { d_ready[i] = 0; d_arr[i] = 0; }
    if (i == 0) {
        d_bcnt = 0u; d_bgen = 0u;
        const int* p = (const int*)ei;
        int all0 = 1;
        for (int j = 1; j < 201; j += 2) all0 &= (p[j] == 0);
        d_is64 = all0;
        for (int j = 0; j < HOR; j++) {
            uint2 r = tf2x32(0u, 42u, 0u, (unsigned)j);
            d_keys[j] = make_uint2(r.x, r.y);
        }
    }
    if (i < 64 * 128) {
        int kp = i >> 7, n = i & 127;
        int o = kp * WSTRIDE + n;
        float le = Wl[n * D + 2 * kp], lo = Wl[n * D + 2 * kp + 1];
        d_wphl[o] = pack_hi(le, lo);
        d_wpll[o] = pack_lo(le, lo);
        float re = Wr[n * D + 2 * kp], ro = Wr[n * D + 2 * kp + 1];
        d_wphr[o] = pack_hi(re, ro);
        d_wplr[o] = pack_lo(re, ro);
    }
    if (i < 64 * 256) {
        int k2 = i >> 8, t = i & 255;
        d_wpih[i] = make_float4(Wih[(2 * t) * D + 2 * k2], Wih[(2 * t) * D + 2 * k2 + 1],
                                Wih[(2 * t + 1) * D + 2 * k2], Wih[(2 * t + 1) * D + 2 * k2 + 1]);
        d_wphh[i] = make_float4(Whh[(2 * t) * D + 2 * k2], Whh[(2 * t) * D + 2 * k2 + 1],
                                Whh[(2 * t + 1) * D + 2 * k2], Whh[(2 * t + 1) * D + 2 * k2 + 1]);
    }
}

// ---------------- combined HMMA GEMM: blocks [0,391) -> xr, [391,1173) -> xl ----------------
#define SM_GB (64 * WSTRIDE)
#define NB_NMD 391
__global__ void __launch_bounds__(256, 2) k_gemm_both(const float* __restrict__ Xm,
                                                      const float* __restrict__ Xs) {
    extern __shared__ uint32_t bs[];
    uint32_t* Bh = bs;
    uint32_t* Bl = bs + SM_GB;
    const float* X; const uint32_t* gbh; const uint32_t* gbl; float* Y; int rows; int b;
    if (blockIdx.x < NB_NMD) { X = Xm; gbh = d_wphr; gbl = d_wplr; Y = d_xr; rows = NMD; b = blockIdx.x; }
    else                     { X = Xs; gbh = d_wphl; gbl = d_wpll; Y = d_xl; rows = NSN; b = blockIdx.x - NB_NMD; }
    for (int i = threadIdx.x; i < SM_GB / 4; i += 256) {
        ((uint4*)Bh)[i] = ((const uint4*)gbh)[i];
        ((uint4*)Bl)[i] = ((const uint4*)gbl)[i];
    }
    __syncthreads();
    int w = threadIdx.x >> 5, lane = threadIdx.x & 31;
    int q = lane & 3, g = lane >> 2;
    int r0 = b * 128 + w * 16 + g;
    const float* x0 = X + (size_t)(r0 < rows ? r0 : rows - 1) * D;
    const float* x1 = X + (size_t)(r0 + 8 < rows ? r0 + 8 : rows - 1) * D;
    float acc[16][4];
#pragma unroll
    for (int nt = 0; nt < 16; nt++) { acc[nt][0] = acc[nt][1] = acc[nt][2] = acc[nt][3] = 0.f; }
#pragma unroll
    for (int k8 = 0; k8 < 8; k8++) {
        int c0 = k8 * 16 + 2 * q;
        float2 p0 = *(const float2*)(x0 + c0);
        float2 p1 = *(const float2*)(x1 + c0);
        float2 p2 = *(const float2*)(x0 + c0 + 8);
        float2 p3 = *(const float2*)(x1 + c0 + 8);
        uint32_t ah[4], al[4];
        ah[0] = pack_hi(p0.x, p0.y); al[0] = pack_lo(p0.x, p0.y);
        ah[1] = pack_hi(p1.x, p1.y); al[1] = pack_lo(p1.x, p1.y);
        ah[2] = pack_hi(p2.x, p2.y); al[2] = pack_lo(p2.x, p2.y);
        ah[3] = pack_hi(p3.x, p3.y); al[3] = pack_lo(p3.x, p3.y);
        int kb0 = (k8 * 8 + q) * WSTRIDE + g;
        int kb1 = (k8 * 8 + q + 4) * WSTRIDE + g;
#pragma unroll
        for (int nt = 0; nt < 16; nt++) {
            uint32_t bh0 = Bh[kb0 + nt * 8];
            uint32_t bh1 = Bh[kb1 + nt * 8];
            uint32_t bl0 = Bl[kb0 + nt * 8];
            uint32_t bl1 = Bl[kb1 + nt * 8];
            mma_bf16(acc[nt], ah, bh0, bh1);
            mma_bf16(acc[nt], ah, bl0, bl1);
            mma_bf16(acc[nt], al, bh0, bh1);
        }
    }
    bool w0 = r0 < rows, w1 = (r0 + 8) < rows;
#pragma unroll
    for (int nt = 0; nt < 16; nt++) {
        int col = nt * 8 + 2 * q;
        if (w0) *(float2*)(Y + (size_t)r0 * D + col) = make_float2(acc[nt][0], acc[nt][1]);
        if (w1) *(float2*)(Y + (size_t)(r0 + 8) * D + col) = make_float2(acc[nt][2], acc[nt][3]);
    }
}

// ---------------- fused edge pass ----------------
__global__ void __launch_bounds__(256) k_edge12(const void* __restrict__ ei,
                                                const float* __restrict__ att) {
    int lane = threadIdx.x & 31;
    int wid = (blockIdx.x * blockDim.x + threadIdx.x) >> 5;
    int nw = (gridDim.x * blockDim.x) >> 5;
    int is64 = d_is64;
    float4 av = ((const float4*)att)[lane];
    for (int e = wid * 2; e < EE; e += nw * 2) {
        int s1 = eidx(ei, is64, e);
        int dd1 = eidx(ei, is64, (long long)EE + e);
        int s2 = eidx(ei, is64, e + 1);
        int dd2 = eidx(ei, is64, (long long)EE + e + 1);
        float4 l1 = ((const float4*)(d_xl + (size_t)s1 * D))[lane];
        float4 r1 = ((const float4*)(d_xr + (size_t)dd1 * D))[lane];
        float4 l2 = ((const float4*)(d_xl + (size_t)s2 * D))[lane];
        float4 r2 = ((const float4*)(d_xr + (size_t)dd2 * D))[lane];
        float zx, zy, zz, zw, p1, p2;
        zx = l1.x + r1.x; zy = l1.y + r1.y; zz = l1.z + r1.z; zw = l1.w + r1.w;
        zx = zx > 0.f ? zx : NEG * zx; zy = zy > 0.f ? zy : NEG * zy;
        zz = zz > 0.f ? zz : NEG * zz; zw = zw > 0.f ? zw : NEG * zw;
        p1 = av.x * zx + av.y * zy + av.z * zz + av.w * zw;
        zx = l2.x + r2.x; zy = l2.y + r2.y; zz = l2.z + r2.z; zw = l2.w + r2.w;
        zx = zx > 0.f ? zx : NEG * zx; zy = zy > 0.f ? zy : NEG * zy;
        zz = zz > 0.f ? zz : NEG * zz; zw = zw > 0.f ? zw : NEG * zw;
        p2 = av.x * zx + av.y * zy + av.z * zz + av.w * zw;
#pragma unroll
        for (int o = 16; o; o >>= 1) {
            p1 += __shfl_xor_sync(~0u, p1, o);
            p2 += __shfl_xor_sync(~0u, p2, o);
        }
        if (lane == 0) {
            float e1 = expf(p1), e2 = expf(p2);
            d_ew[e] = e1;     atomicAdd(&d_ssum[dd1], e1);
            d_ew[e + 1] = e2; atomicAdd(&d_ssum[dd2], e2);
        }
    }
}

// ---------------- mega-kernel: edge3a + dense + fing + 8-step rollout + final ----------------
__global__ void __launch_bounds__(256) k_rollall(
    const void* __restrict__ ei,   const float* __restrict__ cbias,
    const float* __restrict__ bih, const float* __restrict__ bhh,
    const float* __restrict__ W1,  const float* __restrict__ b1,
    const float* __restrict__ W2,  const float* __restrict__ b2,
    const float* __restrict__ emb, float* __restrict__ out) {
    extern __shared__ float w2s[];   // [RPB][RSTRIDE]
    __shared__ float si[D], sh[D], sg[4 * D], snh[D], sh2[D], sden[D];
    __shared__ float wbest[8], wbl[8], wlm[8], wls[8];
    __shared__ int wbi[8], sAct;
    int t = threadIdx.x, lane = t & 31, w = t >> 5;
    const float NI = neginf();
    int is64 = d_is64;

    // ---- phase 1: edge3a (c[src] += ew/ssum[dst]) ----
    for (int i = blockIdx.x * 256 + t; i < EE; i += GLOG * 256) {
        int src = eidx(ei, is64, i);
        int dst = eidx(ei, is64, (long long)EE + i);
        atomicAdd(&d_csrc[src], d_ew[i] / d_ssum[dst]);
    }
    gridbar128();

    // ---- phase 2: dense g += c[r]*xl[r] ----
    if (t < D) sden[t] = 0.f;
    __syncthreads();
    {
        int gw = blockIdx.x * 8 + w;
        float4 acc = make_float4(0.f, 0.f, 0.f, 0.f);
        for (int r = gw; r < NSN; r += GLOG * 8) {
            float cv = d_csrc[r];
            float4 v = ((const float4*)(d_xl + (size_t)r * D))[lane];
            acc.x += cv * v.x; acc.y += cv * v.y; acc.z += cv * v.z; acc.w += cv * v.w;
        }
        atomicAdd(&sden[lane * 4 + 0], acc.x);
        atomicAdd(&sden[lane * 4 + 1], acc.y);
        atomicAdd(&sden[lane * 4 + 2], acc.z);
        atomicAdd(&sden[lane * 4 + 3], acc.w);
        __syncthreads();
        if (t < D) atomicAdd(&d_gacc[t], sden[t]);
    }
    gridbar128();

    // ---- stage this block's W2 slice into smem ----
    int r0 = blockIdx.x * RPB;
    int R = NMD - r0; if (R > RPB) R = RPB;
    for (int idx = t; idx < R * 32; idx += 256) {
        int rloc = idx >> 5, c4 = idx & 31;
        float4 v = ((const float4*)(W2 + (size_t)(r0 + rloc) * D))[c4];
        float* dstp = w2s + rloc * RSTRIDE + c4 * 4;
        dstp[0] = v.x; dstp[1] = v.y; dstp[2] = v.z; dstp[3] = v.w;
    }
    // block 0: pooled input (fing) -> si
    if (blockIdx.x == 0 && t < D) si[t] = d_gacc[t] * (1.0f / (float)NMD) + cbias[t];
    __syncthreads();

    // ---- phase 3: 8-step rollout ----
    for (int step = 0; step < HOR; step++) {
        int wp = step & 1, pmr = (step - 1) & 1;
        if (blockIdx.x == 0) {
            if (step > 0) {
                if (t == 0) { while (*(volatile int*)&d_arr[step - 1] < GLOG) __nanosleep(64); }
                __syncthreads();
                __threadfence();
                if (t < 32) {
                    float B = NI, BL = 0.f; int BI = 0x7fffffff; float M = NI, S = 0.f;
                    for (int i = lane; i < GLOG; i += 32) {
                        float b = d_pm_best[pmr][i]; int bidx = d_pm_bi[pmr][i];
                        if (b > B || (b == B && bidx < BI)) { B = b; BI = bidx; BL = d_pm_bl[pmr][i]; }
                        lsmerge(M, S, d_pm_lm[pmr][i], d_pm_ls[pmr][i]);
                    }
#pragma unroll
                    for (int o = 16; o; o >>= 1) {
                        float ob = __shfl_xor_sync(~0u, B, o);
                        int oi = __shfl_xor_sync(~0u, BI, o);
                        float ol = __shfl_xor_sync(~0u, BL, o);
                        if (ob > B || (ob == B && oi < BI)) { B = ob; BI = oi; BL = ol; }
                        float om = __shfl_xor_sync(~0u, M, o);
                        float os = __shfl_xor_sync(~0u, S, o);
                        lsmerge(M, S, om, os);
                    }
                    if (lane == 0) {
                        out[step - 1] = (float)BI;
                        out[HOR + step - 1] = BL - (M + logf(S));
                        sAct = BI;
                    }
                }
                __syncthreads();
                if (t < D) si[t] = emb[(size_t)sAct * D + t];
            }
            if (t < D) sh[t] = d_h[t];
            __syncthreads();
            {
                float2 bi_ = ((const float2*)bih)[t];
                float2 bh_ = ((const float2*)bhh)[t];
                float ax = bi_.x + bh_.x, ay = bi_.y + bh_.y;
#pragma unroll 4
                for (int k2 = 0; k2 < 64; k2++) {
                    float4 wi = d_wpih[k2 * 256 + t];
                    float4 wh = d_wphh[k2 * 256 + t];
                    float x0 = si[2 * k2], x1 = si[2 * k2 + 1];
                    float h0 = sh[2 * k2], h1 = sh[2 * k2 + 1];
                    ax += wi.x * x0 + wi.y * x1 + wh.x * h0 + wh.y * h1;
                    ay += wi.z * x0 + wi.w * x1 + wh.z * h0 + wh.w * h1;
                }
                sg[2 * t] = ax; sg[2 * t + 1] = ay;
            }
            __syncthreads();
            if (t < D) {
                float ig = 1.f / (1.f + expf(-sg[t]));
                float fg = 1.f / (1.f + expf(-sg[D + t]));
                float gg = tanhf(sg[2 * D + t]);
                float og = 1.f / (1.f + expf(-sg[3 * D + t]));
                float c = fg * d_c[t] + ig * gg;
                float h = og * tanhf(c);
                snh[t] = h;
                d_c[t] = c; d_h[t] = h;
                if (step == HOR - 1) { out[2 * HOR + t] = h; out[2 * HOR + D + t] = c; }
            }
            __syncthreads();
            if (t < D) {
                float a0 = b1[t], a1 = 0.f;
                const float4* w1 = (const float4*)(W1 + (size_t)t * D);
#pragma unroll 8
                for (int k = 0; k < 32; k += 2) {
                    float4 a = w1[k];     float4 hv = *(const float4*)(snh + 4 * k);
                    float4 b = w1[k + 1]; float4 h2v = *(const float4*)(snh + 4 * k + 4);
                    a0 += a.x * hv.x + a.y * hv.y + a.z * hv.z + a.w * hv.w;
                    a1 += b.x * h2v.x + b.y * h2v.y + b.z * h2v.z + b.w * h2v.w;
                }
                float a2 = a0 + a1;
                a2 = a2 > 0.f ? a2 : 0.f;
                sh2[t] = a2;
                d_h2g[t] = a2;
            }
            __syncthreads();
            if (t == 0) { __threadfence(); *(volatile int*)&d_ready[step] = 1; }
        } else {
            if (t == 0) { while (*(volatile int*)&d_ready[step] == 0) __nanosleep(64); }
            __syncthreads();
            __threadfence();
            if (t < D) sh2[t] = __ldcg(&d_h2g[t]);
            __syncthreads();
        }

        // phase B: per-lane-row logits from SMEM + gumbel + online softmax
        uint2 key = d_keys[step];
        float best = NI, bl = 0.f; int bi = 0x7fffffff;
        float lm = NI, ls = 0.f;
        for (int base = w * 32; base < R; base += 256) {
            int rl = base + lane;
            if (rl < R) {
                const float* wrow = w2s + rl * RSTRIDE;
                float a0 = 0.f, a1 = 0.f, a2 = 0.f, a3 = 0.f;
#pragma unroll 8
                for (int c4 = 0; c4 < 32; c4++) {
                    float4 h = ((const float4*)sh2)[c4];
                    a0 += wrow[4 * c4 + 0] * h.x;
                    a1 += wrow[4 * c4 + 1] * h.y;
                    a2 += wrow[4 * c4 + 2] * h.z;
                    a3 += wrow[4 * c4 + 3] * h.w;
                }
                int myrow = r0 + rl;
                float myl = (a0 + a1) + (a2 + a3) + b2[myrow];
                uint2 tr = tf2x32(key.x, key.y, 0u, (unsigned)myrow);
                unsigned bits = tr.x ^ tr.y;
                float u = __uint_as_float((bits >> 9) | 0x3f800000u) - 1.0f;
                if (u == 0.f) u = 1.17549435e-38f;
                float score = myl - logf(-logf(u));
                if (score > best || (score == best && myrow < bi)) { best = score; bi = myrow; bl = myl; }
                lsmerge(lm, ls, myl, 1.f);
            }
        }
#pragma unroll
        for (int o = 16; o; o >>= 1) {
            float ob = __shfl_xor_sync(~0u, best, o);
            int oi = __shfl_xor_sync(~0u, bi, o);
            float ol = __shfl_xor_sync(~0u, bl, o);
            if (ob > best || (ob == best && oi < bi)) { best = ob; bi = oi; bl = ol; }
            float om = __shfl_xor_sync(~0u, lm, o);
            float os = __shfl_xor_sync(~0u, ls, o);
            lsmerge(lm, ls, om, os);
        }
        if (lane == 0) { wbest[w] = best; wbi[w] = bi; wbl[w] = bl; wlm[w] = lm; wls[w] = ls; }
        __syncthreads();
        if (t == 0) {
            float B = NI, BL = 0.f; int BI = 0x7fffffff; float M = NI, S = 0.f;
            for (int i = 0; i < 8; i++) {
                if (wbest[i] > B || (wbest[i] == B && wbi[i] < BI)) { B = wbest[i]; BI = wbi[i]; BL = wbl[i]; }
                lsmerge(M, S, wlm[i], wls[i]);
            }
            d_pm_best[wp][blockIdx.x] = B; d_pm_bi[wp][blockIdx.x] = BI; d_pm_bl[wp][blockIdx.x] = BL;
            d_pm_lm[wp][blockIdx.x] = M;  d_pm_ls[wp][blockIdx.x] = S;
            __threadfence();
            atomicAdd(&d_arr[step], 1);
        }
        __syncthreads();
    }

    // ---- final sample (block 0) ----
    if (blockIdx.x == 0) {
        if (t == 0) { while (*(volatile int*)&d_arr[HOR - 1] < GLOG) __nanosleep(64); }
        __syncthreads();
        __threadfence();
        if (t < 32) {
            int pb = (HOR - 1) & 1;
            float B = NI, BL = 0.f; int BI = 0x7fffffff; float M = NI, S = 0.f;
            for (int i = lane; i < GLOG; i += 32) {
                float b = d_pm_best[pb][i]; int bidx = d_pm_bi[pb][i];
                if (b > B || (b == B && bidx < BI)) { B = b; BI = bidx; BL = d_pm_bl[pb][i]; }
                lsmerge(M, S, d_pm_lm[pb][i], d_pm_ls[pb][i]);
            }
#pragma unroll
            for (int o = 16; o; o >>= 1) {
                float ob = __shfl_xor_sync(~0u, B, o);
                int oi = __shfl_xor_sync(~0u, BI, o);
                float ol = __shfl_xor_sync(~0u, BL, o);
                if (ob > B || (ob == B && oi < BI)) { B = ob; BI = oi; BL = ol; }
                float om = __shfl_xor_sync(~0u, M, o);
                float os = __shfl_xor_sync(~0u, S, o);
                lsmerge(M, S, om, os);
            }
            if (lane == 0) {
                out[HOR - 1] = (float)BI;
                out[2 * HOR - 1] = BL - (M + logf(S));
            }
        }
    }
}

// ---------------- launch ----------------
extern "C" void kernel_launch(void* const* d_in, const int* in_sizes, int n_in,
                              void* d_out, int out_size) {
    const float* state_features = (const float*)d_in[0];
    const float* model_features = (const float*)d_in[1];
    const void*  edge_index     = d_in[2];
    const float* W_l   = (const float*)d_in[3];
    const float* W_r   = (const float*)d_in[4];
    const float* att   = (const float*)d_in[5];
    const float* cbias = (const float*)d_in[6];
    const float* Wih   = (const float*)d_in[7];
    const float* Whh   = (const float*)d_in[8];
    const float* bih   = (const float*)d_in[9];
    const float* bhh   = (const float*)d_in[10];
    const float* W1    = (const float*)d_in[11];
    const float* b1    = (const float*)d_in[12];
    const float* W2    = (const float*)d_in[13];
    const float* b2    = (const float*)d_in[14];
    const float* emb   = (const float*)d_in[15];
    float* out = (float*)d_out;

    const int smemB = 2 * SM_GB * (int)sizeof(uint32_t);        // 69632
    const int smemR = RPB * RSTRIDE * (int)sizeof(float);       // 201756
    cudaFuncSetAttribute(k_gemm_both, cudaFuncAttributeMaxDynamicSharedMemorySize, smemB);
    cudaFuncSetAttribute(k_rollall, cudaFuncAttributeMaxDynamicSharedMemorySize, smemR);

    k_prep<<<391, 256>>>(edge_index, W_l, W_r, Wih, Whh);
    k_gemm_both<<<NB_NMD + 782, 256, smemB>>>(model_features, state_features);
    k_edge12<<<1184, 256>>>(edge_index, att);
    k_rollall<<<GLOG, 256, smemR>>>(edge_index, cbias, bih, bhh, W1, b1, W2, b2, emb, out);  // profiled
    (void)in_sizes; (void)n_in; (void)out_size;
}